// round 13
// baseline (speedup 1.0000x reference)
#include <cuda_runtime.h>
#include <stdint.h>

// ---------------- problem constants ----------------
#define FF     4096
#define JJ     2048
#define PP     8
#define NB6    6
#define HHH    2112      // J + T
#define MB     256       // batch
#define XW     6432
#define OFF_D  96
#define OFF_S  4192
#define OFF_P  6240
#define KDQ    4104      // F + P

// ---------------- scratch (device globals; no runtime allocation) ----------------
#define SZF   (MB*FF)
#define SZH   (MB*HHH)
#define SZADQ (MB*KDQ)

__device__ float g_res_h0q[SZF];
__device__ float g_res_h0h[SZH];
__device__ float g_res_Sq[SZF];
__device__ float g_res_sq[SZF];
__device__ float g_res_qh[SZH];
__device__ float g_q[SZF];
__device__ float g_ADq[SZADQ];
__device__ float g_Dq[SZF];
__device__ float g_Dh[SZH];
__device__ float g_hidx[SZF];
__device__ float g_h[SZH];

// ---------------- fp32 SIMT GEMM ----------------
// C[M,N] = epi( A[M,K] @ W[N,K]^T + bias ),  all fp32.
// epi: 0 = none, 1 = relu, 2 = prelu_sub: C = aux - prelu(acc+bias)
#define TBM 128
#define TBN 64
#define TBK 16
#define NTH 128

__global__ __launch_bounds__(NTH)
void gemm_f32(const float* __restrict__ A, int lda,
              const float* __restrict__ W, int ldw,
              const float* __restrict__ bias,
              float* __restrict__ C, int ldc,
              int K, int epi,
              const float* __restrict__ aux,
              const float* __restrict__ alpha_ptr)
{
    __shared__ float sA[TBK][TBM];   // k-major
    __shared__ float sB[TBK][TBN];

    const int tid = threadIdx.x;
    const int bm  = blockIdx.y;
    const int bn  = blockIdx.x;
    const int tn  = tid & 7;    // 8 threads along N
    const int tm  = tid >> 3;   // 16 threads along M

    const float* Abase = A + (size_t)(bm * TBM) * lda;
    const float* Wbase = W + (size_t)(bn * TBN) * ldw;

    float4 ra[4], rb[2];
    float acc[8][8];
#pragma unroll
    for (int i = 0; i < 8; i++)
#pragma unroll
        for (int j = 0; j < 8; j++) acc[i][j] = 0.f;

    const int nk = (K + TBK - 1) / TBK;

    // ---- first tile: gmem -> regs ----
#pragma unroll
    for (int j = 0; j < 4; j++) {
        int id = tid + NTH * j;
        int r = id >> 2, c4 = (id & 3) << 2;
        ra[j] = (c4 < K) ? *(const float4*)(Abase + (size_t)r * lda + c4)
                         : make_float4(0.f, 0.f, 0.f, 0.f);
    }
#pragma unroll
    for (int j = 0; j < 2; j++) {
        int id = tid + NTH * j;
        int r = id >> 2, c4 = (id & 3) << 2;
        rb[j] = (c4 < K) ? *(const float4*)(Wbase + (size_t)r * ldw + c4)
                         : make_float4(0.f, 0.f, 0.f, 0.f);
    }
    // ---- regs -> smem (transpose to k-major) ----
#pragma unroll
    for (int j = 0; j < 4; j++) {
        int id = tid + NTH * j;
        int r = id >> 2, c4 = (id & 3) << 2;
        sA[c4 + 0][r] = ra[j].x; sA[c4 + 1][r] = ra[j].y;
        sA[c4 + 2][r] = ra[j].z; sA[c4 + 3][r] = ra[j].w;
    }
#pragma unroll
    for (int j = 0; j < 2; j++) {
        int id = tid + NTH * j;
        int r = id >> 2, c4 = (id & 3) << 2;
        sB[c4 + 0][r] = rb[j].x; sB[c4 + 1][r] = rb[j].y;
        sB[c4 + 2][r] = rb[j].z; sB[c4 + 3][r] = rb[j].w;
    }
    __syncthreads();

    for (int t = 0; t < nk; t++) {
        const bool pref = (t + 1 < nk);
        if (pref) {
            const int k0 = (t + 1) * TBK;
#pragma unroll
            for (int j = 0; j < 4; j++) {
                int id = tid + NTH * j;
                int r = id >> 2, c4 = (id & 3) << 2;
                int k = k0 + c4;
                ra[j] = (k < K) ? *(const float4*)(Abase + (size_t)r * lda + k)
                                : make_float4(0.f, 0.f, 0.f, 0.f);
            }
#pragma unroll
            for (int j = 0; j < 2; j++) {
                int id = tid + NTH * j;
                int r = id >> 2, c4 = (id & 3) << 2;
                int k = k0 + c4;
                rb[j] = (k < K) ? *(const float4*)(Wbase + (size_t)r * ldw + k)
                                : make_float4(0.f, 0.f, 0.f, 0.f);
            }
        }

        // ---- compute ----
#pragma unroll
        for (int k = 0; k < TBK; k++) {
            float a[8], b[8];
            *(float4*)&a[0] = *(const float4*)&sA[k][tm * 8 + 0];
            *(float4*)&a[4] = *(const float4*)&sA[k][tm * 8 + 4];
            *(float4*)&b[0] = *(const float4*)&sB[k][tn * 8 + 0];
            *(float4*)&b[4] = *(const float4*)&sB[k][tn * 8 + 4];
#pragma unroll
            for (int i = 0; i < 8; i++)
#pragma unroll
                for (int j = 0; j < 8; j++)
                    acc[i][j] = fmaf(a[i], b[j], acc[i][j]);
        }
        __syncthreads();
        if (pref) {
#pragma unroll
            for (int j = 0; j < 4; j++) {
                int id = tid + NTH * j;
                int r = id >> 2, c4 = (id & 3) << 2;
                sA[c4 + 0][r] = ra[j].x; sA[c4 + 1][r] = ra[j].y;
                sA[c4 + 2][r] = ra[j].z; sA[c4 + 3][r] = ra[j].w;
            }
#pragma unroll
            for (int j = 0; j < 2; j++) {
                int id = tid + NTH * j;
                int r = id >> 2, c4 = (id & 3) << 2;
                sB[c4 + 0][r] = rb[j].x; sB[c4 + 1][r] = rb[j].y;
                sB[c4 + 2][r] = rb[j].z; sB[c4 + 3][r] = rb[j].w;
            }
            __syncthreads();
        }
    }

    // ---- epilogue ----
    float alpha = 0.f;
    if (epi == 2) alpha = __ldg(alpha_ptr);

#pragma unroll
    for (int i = 0; i < 8; i++) {
        int grow = bm * TBM + tm * 8 + i;
#pragma unroll
        for (int j4 = 0; j4 < 8; j4 += 4) {
            int gcol = bn * TBN + tn * 8 + j4;
            float4 bv = *(const float4*)&bias[gcol];
            float4 v;
            v.x = acc[i][j4 + 0] + bv.x;
            v.y = acc[i][j4 + 1] + bv.y;
            v.z = acc[i][j4 + 2] + bv.z;
            v.w = acc[i][j4 + 3] + bv.w;
            if (epi == 1) {
                v.x = fmaxf(v.x, 0.f); v.y = fmaxf(v.y, 0.f);
                v.z = fmaxf(v.z, 0.f); v.w = fmaxf(v.w, 0.f);
            } else if (epi == 2) {
                const float4 qv = *(const float4*)&aux[(size_t)grow * ldc + gcol];
                v.x = qv.x - (v.x >= 0.f ? v.x : alpha * v.x);
                v.y = qv.y - (v.y >= 0.f ? v.y : alpha * v.y);
                v.z = qv.z - (v.z >= 0.f ? v.z : alpha * v.z);
                v.w = qv.w - (v.w >= 0.f ? v.w : alpha * v.w);
            }
            *(float4*)&C[(size_t)grow * ldc + gcol] = v;
        }
    }
}

// ---------------- elementwise kernels ----------------
__global__ void k_init_q(const float* __restrict__ x, float* __restrict__ q) {
    int i = blockIdx.x * blockDim.x + threadIdx.x;
    if (i < MB * FF) {
        int m = i / FF, f = i - m * FF;
        float d = x[(size_t)m * XW + OFF_D + f];
        q[i] = 0.78539816339744830962f * d * d;   // pi/4 * d^2
    }
}

__global__ void k_build_adq(const float* __restrict__ x, const float* __restrict__ q,
                            const float* __restrict__ rSq, float* __restrict__ adq) {
    int i = blockIdx.x * blockDim.x + threadIdx.x;
    if (i < MB * KDQ) {
        int m = i / KDQ, k = i - m * KDQ;
        adq[i] = (k < FF) ? q[(size_t)m * FF + k] * rSq[(size_t)m * FF + k]
                          : x[(size_t)m * XW + OFF_P + (k - FF)];
    }
}

__global__ void k_hidx(const float* __restrict__ Dq, const float* __restrict__ q,
                       const float* __restrict__ rsq, const float* __restrict__ rh0q,
                       float* __restrict__ out) {
    int i = blockIdx.x * blockDim.x + threadIdx.x;
    if (i < MB * FF) out[i] = Dq[i] * (q[i] + rsq[i] + rh0q[i]);
}

__global__ void k_tin(float* __restrict__ h, const float* __restrict__ rh0h,
                      const float* __restrict__ rqh, const float* __restrict__ Dh) {
    int i = blockIdx.x * blockDim.x + threadIdx.x;
    if (i < MB * HHH) h[i] = (h[i] + rh0h[i] + rqh[i]) * Dh[i];
}

// ---------------- host-side orchestration ----------------
static inline void gemm(const float* A, int lda, const float* W, int ldw,
                        const float* bias, float* C, int ldc,
                        int N, int K, int epi,
                        const float* aux, const float* alpha_ptr) {
    dim3 grid(N / TBN, MB / TBM);
    gemm_f32<<<grid, NTH>>>(A, lda, W, ldw, bias, C, ldc, K, epi, aux, alpha_ptr);
}

extern "C" void kernel_launch(void* const* d_in, const int* in_sizes, int n_in,
                              void* d_out, int out_size) {
    const float* x      = (const float*)d_in[0];
    const float* W_h0q  = (const float*)d_in[2];
    const float* b_h0q  = (const float*)d_in[3];
    const float* W_h0h  = (const float*)d_in[4];
    const float* b_h0h  = (const float*)d_in[5];
    const float* W_S    = (const float*)d_in[6];
    const float* b_S    = (const float*)d_in[7];
    const float* W_q0h  = (const float*)d_in[8];
    const float* b_q0h  = (const float*)d_in[9];
    const float* W_sq   = (const float*)d_in[10];
    const float* b_sq   = (const float*)d_in[11];
    const float* W_out  = (const float*)d_in[12];
    const float* b_out  = (const float*)d_in[13];
    const float* W_hf   = (const float*)d_in[14];
    const float* b_hf   = (const float*)d_in[15];
    const float* W_fh   = (const float*)d_in[16];
    const float* b_fh   = (const float*)d_in[17];
    const float* W_resq = (const float*)d_in[18];
    const float* b_resq = (const float*)d_in[19];
    const float* W_Dq   = (const float*)d_in[20];
    const float* b_Dq   = (const float*)d_in[21];
    const float* W_Dh   = (const float*)d_in[22];
    const float* b_Dh   = (const float*)d_in[23];
    const float* prelua = (const float*)d_in[24];

    float *rh0q, *rh0h, *rSq, *rsq, *rqh, *q, *adq, *Dq, *Dh, *hidx, *h;
    cudaGetSymbolAddress((void**)&rh0q, g_res_h0q);
    cudaGetSymbolAddress((void**)&rh0h, g_res_h0h);
    cudaGetSymbolAddress((void**)&rSq,  g_res_Sq);
    cudaGetSymbolAddress((void**)&rsq,  g_res_sq);
    cudaGetSymbolAddress((void**)&rqh,  g_res_qh);
    cudaGetSymbolAddress((void**)&q,    g_q);
    cudaGetSymbolAddress((void**)&adq,  g_ADq);
    cudaGetSymbolAddress((void**)&Dq,   g_Dq);
    cudaGetSymbolAddress((void**)&Dh,   g_Dh);
    cudaGetSymbolAddress((void**)&hidx, g_hidx);
    cudaGetSymbolAddress((void**)&h,    g_h);

    // ---- prologue ----
    gemm(x,          XW, W_h0q, 96,  b_h0q, rh0q, FF,  FF,  96,  0, nullptr, nullptr);
    gemm(x,          XW, W_h0h, 96,  b_h0h, rh0h, HHH, HHH, 96,  0, nullptr, nullptr);
    gemm(x + OFF_D,  XW, W_S,   FF,  b_S,   rSq,  FF,  FF,  FF,  1, nullptr, nullptr);
    k_init_q<<<(MB * FF + 255) / 256, 256>>>(x, q);
    gemm(q,          FF, W_q0h, FF,  b_q0h, rqh,  HHH, HHH, FF,  0, nullptr, nullptr);
    gemm(x + OFF_S,  XW, W_sq,  JJ,  b_sq,  rsq,  FF,  FF,  JJ,  0, nullptr, nullptr);

    // ---- 6 unrolled blocks ----
    for (int i = 0; i < NB6; i++) {
        const float* Wdq_i = W_Dq + (size_t)i * FF * KDQ;
        const float* bdq_i = b_Dq + (size_t)i * FF;
        const float* Wdh_i = W_Dh + (size_t)i * HHH * FF;
        const float* bdh_i = b_Dh + (size_t)i * HHH;
        const float* Wfh_i = W_fh + (size_t)i * HHH * FF;
        const float* bfh_i = b_fh + (size_t)i * HHH;
        const float* Whf_i = W_hf + (size_t)i * FF * HHH;
        const float* bhf_i = b_hf + (size_t)i * FF;
        const float* Wrq_i = W_resq + (size_t)i * HHH * FF;
        const float* brq_i = b_resq + (size_t)i * HHH;

        k_build_adq<<<(MB * KDQ + 255) / 256, 256>>>(x, q, rSq, adq);
        gemm(adq,  KDQ, Wdq_i, KDQ, bdq_i, Dq, FF,  FF,  KDQ, 0, nullptr, nullptr);
        gemm(Dq,   FF,  Wdh_i, FF,  bdh_i, Dh, HHH, HHH, FF,  1, nullptr, nullptr);
        k_hidx<<<(MB * FF + 255) / 256, 256>>>(Dq, q, rsq, rh0q, hidx);
        gemm(hidx, FF,  Wfh_i, FF,  bfh_i, h,  HHH, HHH, FF,  1, nullptr, nullptr);
        k_tin<<<(MB * HHH + 255) / 256, 256>>>(h, rh0h, rqh, Dh);
        gemm(h,    HHH, Whf_i, HHH, bhf_i, q,  FF,  FF,  HHH, 2, q, prelua + i);
        gemm(q,    FF,  Wrq_i, FF,  brq_i, rqh, HHH, HHH, FF, 1, nullptr, nullptr);
    }

    // ---- output ----
    gemm(q, FF, W_out, FF, b_out, (float*)d_out, HHH, HHH, FF, 0, nullptr, nullptr);
}

// round 15
// speedup vs baseline: 1.2515x; 1.2515x over previous
#include <cuda_runtime.h>
#include <stdint.h>

// ---------------- problem constants ----------------
#define FF     4096
#define JJ     2048
#define PP     8
#define NB6    6
#define HHH    2112      // J + T
#define MB     256       // batch
#define XW     6432
#define OFF_D  96
#define OFF_S  4192
#define OFF_P  6240
#define KDQ    4104      // F + P

// ---------------- scratch (device globals; no runtime allocation) ----------------
#define SZF   (MB*FF)
#define SZH   (MB*HHH)
#define SZADQ (MB*KDQ)

__device__ float g_res_h0q[SZF];
__device__ float g_res_h0h[SZH];
__device__ float g_res_Sq[SZF];
__device__ float g_res_sq[SZF];
__device__ float g_res_qh[SZH];
__device__ float g_q[SZF];
__device__ float g_ADq[SZADQ];
__device__ float g_Dq[SZF];
__device__ float g_Dh[SZH];
__device__ float g_hidx[SZF];
__device__ float g_h[SZH];

// ---------------- fp32 SIMT GEMM v2 ----------------
// C[M,N] = epi( A[M,K] @ W[N,K]^T + bias ),  all fp32.
// epi: 0 none
//      1 relu
//      2 prelu_sub:  C = aux1 - prelu(v)          (aux1 may alias C)
//      3 relu+tin:   C = (relu(v) + aux1 + aux2) * aux3
//      4 hidx:       C = v;  C2 = v * (aux1 + aux2 + aux3)
#define TBM 64
#define TBN 64
#define TBK 16
#define NTH 256

__global__ __launch_bounds__(NTH)
void gemm_f32v2(const float* __restrict__ A, int lda,
                const float* __restrict__ W, int ldw,
                const float* __restrict__ bias,
                float* __restrict__ C, int ldc,
                int K, int epi,
                const float* __restrict__ aux1,
                const float* __restrict__ aux2,
                const float* __restrict__ aux3,
                float* __restrict__ C2,
                const float* __restrict__ alpha_ptr)
{
    // double-buffered, k-major: s?[stage][k][m-or-n]
    __shared__ float sA[2][TBK][TBM];
    __shared__ float sB[2][TBK][TBN];

    const int tid = threadIdx.x;
    const int bm  = blockIdx.y;
    const int bn  = blockIdx.x;
    const int tm  = tid >> 4;    // 0..15 -> rows tm*4
    const int tn  = tid & 15;    // 0..15 -> cols tn*4

    const float* Abase = A + (size_t)(bm * TBM) * lda;
    const float* Wbase = W + (size_t)(bn * TBN) * ldw;

    // staging map: r = tid & 63 (row), c4 = (tid >> 6) * 4 (k-offset 0/4/8/12)
    const int sr  = tid & 63;
    const int sc4 = (tid >> 6) << 2;

    float4 ra, rb;
    float acc[4][4];
#pragma unroll
    for (int i = 0; i < 4; i++)
#pragma unroll
        for (int j = 0; j < 4; j++) acc[i][j] = 0.f;

    const int nk = (K + TBK - 1) / TBK;

    // ---- first tile: gmem -> regs -> smem[0] ----
    ra = (sc4 < K) ? *(const float4*)(Abase + (size_t)sr * lda + sc4)
                   : make_float4(0.f, 0.f, 0.f, 0.f);
    rb = (sc4 < K) ? *(const float4*)(Wbase + (size_t)sr * ldw + sc4)
                   : make_float4(0.f, 0.f, 0.f, 0.f);
    sA[0][sc4 + 0][sr] = ra.x; sA[0][sc4 + 1][sr] = ra.y;
    sA[0][sc4 + 2][sr] = ra.z; sA[0][sc4 + 3][sr] = ra.w;
    sB[0][sc4 + 0][sr] = rb.x; sB[0][sc4 + 1][sr] = rb.y;
    sB[0][sc4 + 2][sr] = rb.z; sB[0][sc4 + 3][sr] = rb.w;
    __syncthreads();

    for (int t = 0; t < nk; t++) {
        const int cur = t & 1;
        const bool pref = (t + 1 < nk);
        if (pref) {
            const int k = (t + 1) * TBK + sc4;
            ra = (k < K) ? *(const float4*)(Abase + (size_t)sr * lda + k)
                         : make_float4(0.f, 0.f, 0.f, 0.f);
            rb = (k < K) ? *(const float4*)(Wbase + (size_t)sr * ldw + k)
                         : make_float4(0.f, 0.f, 0.f, 0.f);
        }

        // ---- compute from smem[cur] ----
#pragma unroll
        for (int k = 0; k < TBK; k++) {
            float4 a = *(const float4*)&sA[cur][k][tm * 4];
            float4 b = *(const float4*)&sB[cur][k][tn * 4];
            acc[0][0] = fmaf(a.x, b.x, acc[0][0]);
            acc[0][1] = fmaf(a.x, b.y, acc[0][1]);
            acc[0][2] = fmaf(a.x, b.z, acc[0][2]);
            acc[0][3] = fmaf(a.x, b.w, acc[0][3]);
            acc[1][0] = fmaf(a.y, b.x, acc[1][0]);
            acc[1][1] = fmaf(a.y, b.y, acc[1][1]);
            acc[1][2] = fmaf(a.y, b.z, acc[1][2]);
            acc[1][3] = fmaf(a.y, b.w, acc[1][3]);
            acc[2][0] = fmaf(a.z, b.x, acc[2][0]);
            acc[2][1] = fmaf(a.z, b.y, acc[2][1]);
            acc[2][2] = fmaf(a.z, b.z, acc[2][2]);
            acc[2][3] = fmaf(a.z, b.w, acc[2][3]);
            acc[3][0] = fmaf(a.w, b.x, acc[3][0]);
            acc[3][1] = fmaf(a.w, b.y, acc[3][1]);
            acc[3][2] = fmaf(a.w, b.z, acc[3][2]);
            acc[3][3] = fmaf(a.w, b.w, acc[3][3]);
        }

        // ---- stage next tile into the other buffer ----
        if (pref) {
            const int nxt = cur ^ 1;
            sA[nxt][sc4 + 0][sr] = ra.x; sA[nxt][sc4 + 1][sr] = ra.y;
            sA[nxt][sc4 + 2][sr] = ra.z; sA[nxt][sc4 + 3][sr] = ra.w;
            sB[nxt][sc4 + 0][sr] = rb.x; sB[nxt][sc4 + 1][sr] = rb.y;
            sB[nxt][sc4 + 2][sr] = rb.z; sB[nxt][sc4 + 3][sr] = rb.w;
        }
        __syncthreads();
    }

    // ---- epilogue ----
    float alpha = 0.f;
    if (epi == 2) alpha = __ldg(alpha_ptr);

    const int gcol = bn * TBN + tn * 4;
    const float4 bv = *(const float4*)&bias[gcol];

#pragma unroll
    for (int i = 0; i < 4; i++) {
        const int grow = bm * TBM + tm * 4 + i;
        const size_t idx = (size_t)grow * ldc + gcol;
        float4 v;
        v.x = acc[i][0] + bv.x;
        v.y = acc[i][1] + bv.y;
        v.z = acc[i][2] + bv.z;
        v.w = acc[i][3] + bv.w;

        if (epi == 1) {
            v.x = fmaxf(v.x, 0.f); v.y = fmaxf(v.y, 0.f);
            v.z = fmaxf(v.z, 0.f); v.w = fmaxf(v.w, 0.f);
        } else if (epi == 2) {
            const float4 qv = *(const float4*)&aux1[idx];
            v.x = qv.x - (v.x >= 0.f ? v.x : alpha * v.x);
            v.y = qv.y - (v.y >= 0.f ? v.y : alpha * v.y);
            v.z = qv.z - (v.z >= 0.f ? v.z : alpha * v.z);
            v.w = qv.w - (v.w >= 0.f ? v.w : alpha * v.w);
        } else if (epi == 3) {
            const float4 a1 = *(const float4*)&aux1[idx];
            const float4 a2 = *(const float4*)&aux2[idx];
            const float4 a3 = *(const float4*)&aux3[idx];
            v.x = (fmaxf(v.x, 0.f) + a1.x + a2.x) * a3.x;
            v.y = (fmaxf(v.y, 0.f) + a1.y + a2.y) * a3.y;
            v.z = (fmaxf(v.z, 0.f) + a1.z + a2.z) * a3.z;
            v.w = (fmaxf(v.w, 0.f) + a1.w + a2.w) * a3.w;
        } else if (epi == 4) {
            const float4 a1 = *(const float4*)&aux1[idx];
            const float4 a2 = *(const float4*)&aux2[idx];
            const float4 a3 = *(const float4*)&aux3[idx];
            float4 h;
            h.x = v.x * (a1.x + a2.x + a3.x);
            h.y = v.y * (a1.y + a2.y + a3.y);
            h.z = v.z * (a1.z + a2.z + a3.z);
            h.w = v.w * (a1.w + a2.w + a3.w);
            *(float4*)&C2[idx] = h;
        }
        *(float4*)&C[idx] = v;
    }
}

// ---------------- elementwise kernels ----------------
__global__ void k_init_q(const float* __restrict__ x, float* __restrict__ q) {
    int i = blockIdx.x * blockDim.x + threadIdx.x;
    if (i < MB * FF) {
        int m = i / FF, f = i - m * FF;
        float d = x[(size_t)m * XW + OFF_D + f];
        q[i] = 0.78539816339744830962f * d * d;   // pi/4 * d^2
    }
}

__global__ void k_build_adq(const float* __restrict__ x, const float* __restrict__ q,
                            const float* __restrict__ rSq, float* __restrict__ adq) {
    int i = blockIdx.x * blockDim.x + threadIdx.x;
    if (i < MB * KDQ) {
        int m = i / KDQ, k = i - m * KDQ;
        adq[i] = (k < FF) ? q[(size_t)m * FF + k] * rSq[(size_t)m * FF + k]
                          : x[(size_t)m * XW + OFF_P + (k - FF)];
    }
}

// ---------------- host-side orchestration ----------------
static inline void gemm(const float* A, int lda, const float* W, int ldw,
                        const float* bias, float* C, int ldc,
                        int N, int K, int epi,
                        const float* aux1, const float* aux2, const float* aux3,
                        float* C2, const float* alpha_ptr) {
    dim3 grid(N / TBN, MB / TBM);
    gemm_f32v2<<<grid, NTH>>>(A, lda, W, ldw, bias, C, ldc, K, epi,
                              aux1, aux2, aux3, C2, alpha_ptr);
}

extern "C" void kernel_launch(void* const* d_in, const int* in_sizes, int n_in,
                              void* d_out, int out_size) {
    const float* x      = (const float*)d_in[0];
    const float* W_h0q  = (const float*)d_in[2];
    const float* b_h0q  = (const float*)d_in[3];
    const float* W_h0h  = (const float*)d_in[4];
    const float* b_h0h  = (const float*)d_in[5];
    const float* W_S    = (const float*)d_in[6];
    const float* b_S    = (const float*)d_in[7];
    const float* W_q0h  = (const float*)d_in[8];
    const float* b_q0h  = (const float*)d_in[9];
    const float* W_sq   = (const float*)d_in[10];
    const float* b_sq   = (const float*)d_in[11];
    const float* W_out  = (const float*)d_in[12];
    const float* b_out  = (const float*)d_in[13];
    const float* W_hf   = (const float*)d_in[14];
    const float* b_hf   = (const float*)d_in[15];
    const float* W_fh   = (const float*)d_in[16];
    const float* b_fh   = (const float*)d_in[17];
    const float* W_resq = (const float*)d_in[18];
    const float* b_resq = (const float*)d_in[19];
    const float* W_Dq   = (const float*)d_in[20];
    const float* b_Dq   = (const float*)d_in[21];
    const float* W_Dh   = (const float*)d_in[22];
    const float* b_Dh   = (const float*)d_in[23];
    const float* prelua = (const float*)d_in[24];

    float *rh0q, *rh0h, *rSq, *rsq, *rqh, *q, *adq, *Dq, *Dh, *hidx, *h;
    cudaGetSymbolAddress((void**)&rh0q, g_res_h0q);
    cudaGetSymbolAddress((void**)&rh0h, g_res_h0h);
    cudaGetSymbolAddress((void**)&rSq,  g_res_Sq);
    cudaGetSymbolAddress((void**)&rsq,  g_res_sq);
    cudaGetSymbolAddress((void**)&rqh,  g_res_qh);
    cudaGetSymbolAddress((void**)&q,    g_q);
    cudaGetSymbolAddress((void**)&adq,  g_ADq);
    cudaGetSymbolAddress((void**)&Dq,   g_Dq);
    cudaGetSymbolAddress((void**)&Dh,   g_Dh);
    cudaGetSymbolAddress((void**)&hidx, g_hidx);
    cudaGetSymbolAddress((void**)&h,    g_h);

    // ---- prologue ----
    gemm(x,          XW, W_h0q, 96,  b_h0q, rh0q, FF,  FF,  96,  0, 0, 0, 0, 0, 0);
    gemm(x,          XW, W_h0h, 96,  b_h0h, rh0h, HHH, HHH, 96,  0, 0, 0, 0, 0, 0);
    gemm(x + OFF_D,  XW, W_S,   FF,  b_S,   rSq,  FF,  FF,  FF,  1, 0, 0, 0, 0, 0);
    k_init_q<<<(MB * FF + 255) / 256, 256>>>(x, q);
    gemm(q,          FF, W_q0h, FF,  b_q0h, rqh,  HHH, HHH, FF,  0, 0, 0, 0, 0, 0);
    gemm(x + OFF_S,  XW, W_sq,  JJ,  b_sq,  rsq,  FF,  FF,  JJ,  0, 0, 0, 0, 0, 0);

    // ---- 6 unrolled blocks ----
    for (int i = 0; i < NB6; i++) {
        const float* Wdq_i = W_Dq + (size_t)i * FF * KDQ;
        const float* bdq_i = b_Dq + (size_t)i * FF;
        const float* Wdh_i = W_Dh + (size_t)i * HHH * FF;
        const float* bdh_i = b_Dh + (size_t)i * HHH;
        const float* Wfh_i = W_fh + (size_t)i * HHH * FF;
        const float* bfh_i = b_fh + (size_t)i * HHH;
        const float* Whf_i = W_hf + (size_t)i * FF * HHH;
        const float* bhf_i = b_hf + (size_t)i * FF;
        const float* Wrq_i = W_resq + (size_t)i * HHH * FF;
        const float* brq_i = b_resq + (size_t)i * HHH;

        k_build_adq<<<(MB * KDQ + 255) / 256, 256>>>(x, q, rSq, adq);
        // Dq gemm + fused hidx = Dq*(q+rsq+rh0q)
        gemm(adq,  KDQ, Wdq_i, KDQ, bdq_i, Dq, FF,  FF,  KDQ, 4, q, rsq, rh0q, hidx, 0);
        // Dh = relu(lin(Dq))
        gemm(Dq,   FF,  Wdh_i, FF,  bdh_i, Dh, HHH, HHH, FF,  1, 0, 0, 0, 0, 0);
        // h = (relu(lin(hidx)) + rh0h + rqh) * Dh   (tin fused)
        gemm(hidx, FF,  Wfh_i, FF,  bfh_i, h,  HHH, HHH, FF,  3, rh0h, rqh, Dh, 0, 0);
        // q = q - prelu(lin(h))
        gemm(h,    HHH, Whf_i, HHH, bhf_i, q,  FF,  FF,  HHH, 2, q, 0, 0, 0, prelua + i);
        // rqh = relu(lin(q))
        gemm(q,    FF,  Wrq_i, FF,  brq_i, rqh, HHH, HHH, FF, 1, 0, 0, 0, 0, 0);
    }

    // ---- output ----
    gemm(q, FF, W_out, FF, b_out, (float*)d_out, HHH, HHH, FF, 0, 0, 0, 0, 0, 0);
}